// round 14
// baseline (speedup 1.0000x reference)
#include <cuda_runtime.h>
#include <cuda_fp16.h>
#include <math.h>
#include <stdint.h>

// Problem constants (match reference_code)
#define NN 50000
#define EE 400000
#define BB 50

// ---------------- scratch (static device allocations: allowed) ----------------
__device__ __align__(16) float  g_bufA[(size_t)NN * 64];
__device__ __align__(16) float  g_bufB[(size_t)NN * 64];
__device__ __align__(16) __half g_bufH[(size_t)NN * 256];   // gather out (GEMM in)
__device__ __align__(16) __half g_bufH2[(size_t)NN * 256];  // x4 (L4 GEMM out, half)
__device__ __align__(16) __half g_bufH3[(size_t)NN * 64];   // x3 (L3 out, half)
__device__ __align__(16) __half g_bufH5[(size_t)NN * 512];  // x5 (L5 GEMM out, half)
__device__ __align__(16) float  g_dinv[NN];
__device__ __align__(16) float  g_self[NN];
__device__ __align__(16) float  g_ew[EE];
__device__ __align__(16) __half g_w4h[256 * 64];    // W4^T half [256][64]
__device__ __align__(16) __half g_w5h[512 * 256];   // W5^T half [512][256]
__device__ int   g_degi[NN];
__device__ int   g_rowptr[NN + 1];
__device__ int   g_cursor[NN];
__device__ int   g_esrc[EE];
__device__ int   g_bsum[64];
__device__ int   g_is64;

__device__ __forceinline__ float* selbuf(int w) { return (w == 0) ? g_bufA : g_bufB; }

__device__ __forceinline__ int ld_idx(const void* p, long long i) {
    if (g_is64) return (int)((const long long*)p)[i];
    return ((const int*)p)[i];
}

__device__ __forceinline__ uint32_t smem_u32(const void* p) {
    uint32_t a;
    asm("{ .reg .u64 t; cvta.to.shared.u64 t, %1; cvt.u32.u64 %0, t; }" : "=r"(a) : "l"(p));
    return a;
}

// ---------------- zero + dtype detection (fused) ----------------
__global__ void zero_detect_kernel(const int* __restrict__ ei32, int N) {
    int t = blockIdx.x * blockDim.x + threadIdx.x;
    if (t < N) g_degi[t] = 0;
    if (t == 0) {
        int all0 = 1;
        for (int i = 1; i < 4096; i += 2) {
            if (ei32[i] != 0) { all0 = 0; break; }
        }
        g_is64 = all0;
    }
}

__global__ void deg_accum_kernel(const void* __restrict__ ei, int E) {
    int t = blockIdx.x * blockDim.x + threadIdx.x;
    if (t < E) atomicAdd(&g_degi[ld_idx(ei, (long long)E + t)], 1);
}

__global__ void scan_phase1(int N) {
    __shared__ int warp_tot[32];
    int i    = blockIdx.x * 1024 + threadIdx.x;
    int lane = threadIdx.x & 31, wid = threadIdx.x >> 5;
    int v = (i < N) ? g_degi[i] : 0;
    int incl = v;
#pragma unroll
    for (int off = 1; off < 32; off <<= 1) {
        int u = __shfl_up_sync(0xffffffffu, incl, off);
        if (lane >= off) incl += u;
    }
    if (lane == 31) warp_tot[wid] = incl;
    __syncthreads();
    if (wid == 0) {
        int w = warp_tot[lane];
#pragma unroll
        for (int off = 1; off < 32; off <<= 1) {
            int u = __shfl_up_sync(0xffffffffu, w, off);
            if (lane >= off) w += u;
        }
        warp_tot[lane] = w;
    }
    __syncthreads();
    if (wid > 0) incl += warp_tot[wid - 1];
    if (i < N) g_rowptr[i] = incl;
    if (threadIdx.x == 1023) g_bsum[blockIdx.x] = incl;
}

// phase2 (block-offset) folded in: warp 0 computes sum of bsum[0..bid-1].
__global__ void scan_phase3(int N) {
    __shared__ int s_off;
    int bid = blockIdx.x;
    if (threadIdx.x < 32) {
        int lane = threadIdx.x;
        int v = 0;
        if (lane < bid) v += g_bsum[lane];
        if (lane + 32 < bid) v += g_bsum[lane + 32];
#pragma unroll
        for (int off = 16; off > 0; off >>= 1)
            v += __shfl_down_sync(0xffffffffu, v, off);
        if (lane == 0) s_off = v;
    }
    __syncthreads();
    int i = bid * 1024 + threadIdx.x;
    if (i >= N) return;
    int v    = g_degi[i];
    int incl = g_rowptr[i] + s_off;
    int excl = incl - v;
    g_rowptr[i] = excl;
    g_cursor[i] = excl;
    float d  = (float)v + 1.0f;
    float di = rsqrtf(d);
    g_dinv[i] = di;
    g_self[i] = di * di;
    if (i == N - 1) g_rowptr[N] = incl;
}

__global__ void fill_kernel(const void* __restrict__ ei, int E) {
    int e = blockIdx.x * blockDim.x + threadIdx.x;
    if (e >= E) return;
    int s = ld_idx(ei, e);
    int d = ld_idx(ei, (long long)E + e);
    int p = atomicAdd(&g_cursor[d], 1);
    g_esrc[p] = s;
    g_ew[p]   = g_dinv[s] * g_dinv[d];
}

// ---------------- both W transposes in one launch (z selects) ----------------
__global__ void trconv_both_kernel(const float* __restrict__ W4,
                                   const float* __restrict__ W5) {
    __shared__ float tile[32][33];
    const float* in = (blockIdx.z == 0) ? W4 : W5;
    __half* out = (blockIdx.z == 0) ? g_w4h : g_w5h;
    int R  = (blockIdx.z == 0) ? 64 : 256;
    int Cc = (blockIdx.z == 0) ? 256 : 512;
    int c0 = blockIdx.x * 32, r0 = blockIdx.y * 32;
    if (c0 >= Cc || r0 >= R) return;
    int tx = threadIdx.x;
    for (int i = threadIdx.y; i < 32; i += 8) {
        int r = r0 + i, c = c0 + tx;
        tile[i][tx] = (r < R && c < Cc) ? in[(size_t)r * Cc + c] : 0.f;
    }
    __syncthreads();
    for (int i = threadIdx.y; i < 32; i += 8) {
        int orow = c0 + i, oc = r0 + tx;
        if (orow < Cc && oc < R) out[(size_t)orow * R + oc] = __float2half_rn(tile[tx][i]);
    }
}

// ---------------- layer 1 matmul (32 -> 8) ----------------
__global__ void mm1_kernel(const float* __restrict__ x,
                           const float* __restrict__ W, int N) {
    __shared__ float Ws[32 * 8];
    for (int i = threadIdx.x; i < 32 * 8; i += blockDim.x) Ws[i] = W[i];
    __syncthreads();
    int t = blockIdx.x * blockDim.x + threadIdx.x;
    int n = t >> 3, c = t & 7;
    if (n >= N) return;
    float acc = 0.0f;
    const float* xr = x + (size_t)n * 32;
#pragma unroll
    for (int k = 0; k < 32; k++) acc = fmaf(xr[k], Ws[k * 8 + c], acc);
    g_bufA[(size_t)n * 8 + c] = acc;
}

// ---------------- plain CSR gather (fp32), for L1 ----------------
template <int D4, int BIAS>
__global__ void gather_agg_kernel(int inW, int outW,
                                  const float* __restrict__ bias, int N) {
    int t = blockIdx.x * blockDim.x + threadIdx.x;
    int n = t / D4, c4 = t % D4;
    if (n >= N) return;
    const float4* in4  = (const float4*)selbuf(inW);
    float4*       out4 = (float4*)selbuf(outW);

    float4 b = make_float4(0.f, 0.f, 0.f, 0.f);
    if (BIAS) b = ((const float4*)bias)[c4];

    float4 acc = in4[(size_t)n * D4 + c4];
    if (BIAS) {
        acc.x = fmaxf(acc.x + b.x, 0.f);
        acc.y = fmaxf(acc.y + b.y, 0.f);
        acc.z = fmaxf(acc.z + b.z, 0.f);
        acc.w = fmaxf(acc.w + b.w, 0.f);
    }
    float sn = g_self[n];
    acc.x *= sn; acc.y *= sn; acc.z *= sn; acc.w *= sn;

    int p0 = g_rowptr[n], p1 = g_rowptr[n + 1];
    for (int p = p0; p < p1; p++) {
        int   s = g_esrc[p];
        float w = g_ew[p];
        float4 v = in4[(size_t)s * D4 + c4];
        if (BIAS) {
            v.x = fmaxf(v.x + b.x, 0.f);
            v.y = fmaxf(v.y + b.y, 0.f);
            v.z = fmaxf(v.z + b.z, 0.f);
            v.w = fmaxf(v.w + b.w, 0.f);
        }
        acc.x = fmaf(v.x, w, acc.x);
        acc.y = fmaf(v.y, w, acc.y);
        acc.z = fmaf(v.z, w, acc.z);
        acc.w = fmaf(v.w, w, acc.w);
    }
    out4[(size_t)n * D4 + c4] = acc;
}

// ---------------- fused gather (dim K) + matmul K->OUT + bias2+relu ----------
// OUTH=1 -> write half to g_bufH3; else fp32 to selbuf(outW).
template <int K, int OUT, int NPB, int BIAS1, int OUTH>
__global__ void fused_gather_mm_kernel(int inW, int outW,
                                       const float* __restrict__ b1,
                                       const float* __restrict__ W,
                                       const float* __restrict__ b2, int N) {
    constexpr int D4  = K / 4;
    constexpr int THR = NPB * D4;
    __shared__ float agg[NPB][K];
    __shared__ float Ws[K * OUT];
    __shared__ float bs[OUT];

    const float4* in4 = (const float4*)selbuf(inW);
    float*        C   = selbuf(outW);
    const int tid = threadIdx.x;
    const int nb0 = blockIdx.x * NPB;

    for (int i = tid; i < K * OUT; i += THR) Ws[i] = W[i];
    for (int i = tid; i < OUT; i += THR) bs[i] = b2[i];

    // phase 1: gather
    {
        int nl = tid / D4, c4 = tid % D4;
        int n  = nb0 + nl;
        if (n < N) {
            float4 b = make_float4(0.f, 0.f, 0.f, 0.f);
            if (BIAS1) b = ((const float4*)b1)[c4];
            float4 acc = in4[(size_t)n * D4 + c4];
            if (BIAS1) {
                acc.x = fmaxf(acc.x + b.x, 0.f);
                acc.y = fmaxf(acc.y + b.y, 0.f);
                acc.z = fmaxf(acc.z + b.z, 0.f);
                acc.w = fmaxf(acc.w + b.w, 0.f);
            }
            float sn = g_self[n];
            acc.x *= sn; acc.y *= sn; acc.z *= sn; acc.w *= sn;
            int p0 = g_rowptr[n], p1 = g_rowptr[n + 1];
            for (int p = p0; p < p1; p++) {
                int   s = g_esrc[p];
                float w = g_ew[p];
                float4 v = in4[(size_t)s * D4 + c4];
                if (BIAS1) {
                    v.x = fmaxf(v.x + b.x, 0.f);
                    v.y = fmaxf(v.y + b.y, 0.f);
                    v.z = fmaxf(v.z + b.z, 0.f);
                    v.w = fmaxf(v.w + b.w, 0.f);
                }
                acc.x = fmaf(v.x, w, acc.x);
                acc.y = fmaf(v.y, w, acc.y);
                acc.z = fmaf(v.z, w, acc.z);
                acc.w = fmaf(v.w, w, acc.w);
            }
            *(float4*)&agg[nl][c4 * 4] = acc;
        }
    }
    __syncthreads();

    // phase 2: matmul from smem
    {
        constexpr int CPT = OUT * NPB / THR;     // cols per thread
        constexpr int TPN = OUT / CPT;           // threads per node
        int nl = tid / TPN, cb = (tid % TPN) * CPT;
        int n  = nb0 + nl;
        if (n >= N) return;
        float acc[CPT];
#pragma unroll
        for (int j = 0; j < CPT; j++) acc[j] = bs[cb + j];
#pragma unroll
        for (int k = 0; k < K; k++) {
            float a = agg[nl][k];
#pragma unroll
            for (int j = 0; j < CPT; j++)
                acc[j] = fmaf(a, Ws[k * OUT + cb + j], acc[j]);
        }
#pragma unroll
        for (int j = 0; j < CPT; j += 4) {
            float v0 = fmaxf(acc[j + 0], 0.f);
            float v1 = fmaxf(acc[j + 1], 0.f);
            float v2 = fmaxf(acc[j + 2], 0.f);
            float v3 = fmaxf(acc[j + 3], 0.f);
            if (OUTH) {
                __half2 h0 = __float22half2_rn(make_float2(v0, v1));
                __half2 h1 = __float22half2_rn(make_float2(v2, v3));
                *(__half2*)&g_bufH3[(size_t)n * OUT + cb + j]     = h0;
                *(__half2*)&g_bufH3[(size_t)n * OUT + cb + j + 2] = h1;
            } else {
                float4 o; o.x = v0; o.y = v1; o.z = v2; o.w = v3;
                *(float4*)&C[(size_t)n * OUT + cb + j] = o;
            }
        }
    }
}

// ---------------- CSR gather (half in, half out), edge loop unrolled x2 ------
struct alignas(8) h4 { __half2 a, b; };
template <int D4>
__global__ void gather_agg_hh_kernel(const __half* __restrict__ in, int N) {
    int t = blockIdx.x * blockDim.x + threadIdx.x;
    int n = t / D4, c4 = t % D4;
    if (n >= N) return;
    const h4* in4 = (const h4*)in;

    h4 raw = in4[(size_t)n * D4 + c4];
    float2 l0 = __half22float2(raw.a), l1 = __half22float2(raw.b);
    float sn = g_self[n];
    float4 acc = make_float4(l0.x * sn, l0.y * sn, l1.x * sn, l1.y * sn);

    int p0 = g_rowptr[n], p1 = g_rowptr[n + 1];
    int p = p0;
    for (; p + 1 < p1; p += 2) {
        int   s0 = g_esrc[p],     s1 = g_esrc[p + 1];
        float w0 = g_ew[p];
        float w1 = g_ew[p + 1];
        h4 r0 = in4[(size_t)s0 * D4 + c4];
        h4 r1 = in4[(size_t)s1 * D4 + c4];
        float2 a0 = __half22float2(r0.a), a1 = __half22float2(r0.b);
        float2 b0 = __half22float2(r1.a), b1 = __half22float2(r1.b);
        acc.x = fmaf(a0.x, w0, acc.x); acc.y = fmaf(a0.y, w0, acc.y);
        acc.z = fmaf(a1.x, w0, acc.z); acc.w = fmaf(a1.y, w0, acc.w);
        acc.x = fmaf(b0.x, w1, acc.x); acc.y = fmaf(b0.y, w1, acc.y);
        acc.z = fmaf(b1.x, w1, acc.z); acc.w = fmaf(b1.y, w1, acc.w);
    }
    if (p < p1) {
        int   s = g_esrc[p];
        float w = g_ew[p];
        h4 rv = in4[(size_t)s * D4 + c4];
        float2 v0 = __half22float2(rv.a), v1 = __half22float2(rv.b);
        acc.x = fmaf(v0.x, w, acc.x); acc.y = fmaf(v0.y, w, acc.y);
        acc.z = fmaf(v1.x, w, acc.z); acc.w = fmaf(v1.y, w, acc.w);
    }
    h4 o;
    o.a = __float22half2_rn(make_float2(acc.x, acc.y));
    o.b = __float22half2_rn(make_float2(acc.z, acc.w));
    ((h4*)g_bufH)[(size_t)n * D4 + c4] = o;
}

// ---------------- fp16 m16n8k16 GEMM with cp.async 4-stage pipeline ----------
// OUTSEL: 1 -> half to g_bufH2 (x4), 2 -> half to g_bufH5 (x5).
#define HSTAGES 4
#define H_PITCH 24
#define H_STG (128 * H_PITCH)
#define HGEMM_SMEM (HSTAGES * 2 * H_STG * 2)

template <int OUTSEL>
__global__ __launch_bounds__(256, 2)
void hgemm_kernel(int wsel, const float* __restrict__ bias,
                  int N, int K, int OUT) {
    extern __shared__ __half smh[];
    const uint32_t sbase = smem_u32(smh);

    const __half* Ah = g_bufH;
    const __half* Wt = (wsel == 4) ? g_w4h : g_w5h;
    __half*       Ch = (OUTSEL == 1) ? g_bufH2 : g_bufH5;

    const int tid    = threadIdx.x;
    const int lane   = tid & 31;
    const int warpId = tid >> 5;
    const int warpM  = warpId & 1;
    const int warpN  = warpId >> 1;
    const int gid    = lane >> 2;
    const int tig    = lane & 3;
    const int block_row = blockIdx.x * 128;
    const int block_col = blockIdx.y * 128;

    float c[4][4][4];
#pragma unroll
    for (int i = 0; i < 4; i++)
#pragma unroll
        for (int j = 0; j < 4; j++)
#pragma unroll
            for (int r = 0; r < 4; r++) c[i][j][r] = 0.0f;

    auto load_stage = [&](int st, int k0) {
#pragma unroll
        for (int it = 0; it < 2; it++) {
            int chunk = tid + it * 256;
            if (chunk < 256) {
                int r = chunk >> 1, c8 = (chunk & 1) * 8;
                int grow = block_row + r;
                const __half* src = &Ah[(size_t)grow * K + k0 + c8];
                uint32_t dst = sbase + (st * H_STG + r * H_PITCH + c8) * 2;
                uint32_t pred = (grow < N) ? 1u : 0u;
                asm volatile(
                    "{ .reg .pred p; setp.ne.u32 p, %2, 0;\n\t"
                    "@p cp.async.cg.shared.global [%0], [%1], 16; }"
                    :: "r"(dst), "l"(src), "r"(pred) : "memory");
            } else {
                int c2 = chunk - 256;
                int r = c2 >> 1, c8 = (c2 & 1) * 8;
                const __half* src = &Wt[(size_t)(block_col + r) * K + k0 + c8];
                uint32_t dst = sbase + (HSTAGES * H_STG + st * H_STG + r * H_PITCH + c8) * 2;
                asm volatile("cp.async.cg.shared.global [%0], [%1], 16;"
                             :: "r"(dst), "l"(src) : "memory");
            }
        }
    };

    const int ntiles = K >> 4;
    const int pre = (ntiles < 3) ? ntiles : 3;
    for (int st = 0; st < pre; st++) {
        load_stage(st, st * 16);
        asm volatile("cp.async.commit_group;" ::: "memory");
    }

    for (int ti = 0; ti < ntiles; ti++) {
        asm volatile("cp.async.wait_group 2;" ::: "memory");
        __syncthreads();
        int nxt = ti + 3;
        if (nxt < ntiles) load_stage(nxt & 3, nxt * 16);
        asm volatile("cp.async.commit_group;" ::: "memory");

        const int st = ti & 3;
        const __half* As = &smh[st * H_STG];
        const __half* Bs = &smh[HSTAGES * H_STG + st * H_STG];

        unsigned a[4][4], b[4][2];
#pragma unroll
        for (int mt = 0; mt < 4; mt++) {
            int mb = warpM * 64 + mt * 16;
            a[mt][0] = *(const unsigned*)&As[(mb + gid) * H_PITCH + 2 * tig];
            a[mt][1] = *(const unsigned*)&As[(mb + gid + 8) * H_PITCH + 2 * tig];
            a[mt][2] = *(const unsigned*)&As[(mb + gid) * H_PITCH + 2 * tig + 8];
            a[mt][3] = *(const unsigned*)&As[(mb + gid + 8) * H_PITCH + 2 * tig + 8];
        }
#pragma unroll
        for (int nt = 0; nt < 4; nt++) {
            int nb = warpN * 32 + nt * 8;
            b[nt][0] = *(const unsigned*)&Bs[(nb + gid) * H_PITCH + 2 * tig];
            b[nt][1] = *(const unsigned*)&Bs[(nb + gid) * H_PITCH + 2 * tig + 8];
        }
#pragma unroll
        for (int mt = 0; mt < 4; mt++)
#pragma unroll
            for (int nt = 0; nt < 4; nt++) {
                asm volatile(
                    "mma.sync.aligned.m16n8k16.row.col.f32.f16.f16.f32 "
                    "{%0,%1,%2,%3}, {%4,%5,%6,%7}, {%8,%9}, {%0,%1,%2,%3};"
                    : "+f"(c[mt][nt][0]), "+f"(c[mt][nt][1]),
                      "+f"(c[mt][nt][2]), "+f"(c[mt][nt][3])
                    : "r"(a[mt][0]), "r"(a[mt][1]), "r"(a[mt][2]), "r"(a[mt][3]),
                      "r"(b[nt][0]), "r"(b[nt][1]));
            }
    }

    // Epilogue: bias + relu -> half
#pragma unroll
    for (int mt = 0; mt < 4; mt++) {
        int row0 = block_row + warpM * 64 + mt * 16 + gid;
#pragma unroll
        for (int nt = 0; nt < 4; nt++) {
            int col = block_col + warpN * 32 + nt * 8 + tig * 2;
            float bx = bias[col], by = bias[col + 1];
            float v0x = fmaxf(c[mt][nt][0] + bx, 0.f);
            float v0y = fmaxf(c[mt][nt][1] + by, 0.f);
            float v1x = fmaxf(c[mt][nt][2] + bx, 0.f);
            float v1y = fmaxf(c[mt][nt][3] + by, 0.f);
            if (row0 < N)
                *(__half2*)&Ch[(size_t)row0 * OUT + col] =
                    __float22half2_rn(make_float2(v0x, v0y));
            if (row0 + 8 < N)
                *(__half2*)&Ch[(size_t)(row0 + 8) * OUT + col] =
                    __float22half2_rn(make_float2(v1x, v1y));
        }
    }
}

// ---------------- mean pool over sorted batch ids (half x5 input) -----------
__device__ __forceinline__ int lower_bound_idx(const void* a, int n, int v) {
    int lo = 0, hi = n;
    while (lo < hi) {
        int m = (lo + hi) >> 1;
        if (ld_idx(a, m) < v) lo = m + 1; else hi = m;
    }
    return lo;
}

__global__ void pool_kernel(const void* __restrict__ batch,
                            float* __restrict__ out, int N, int B) {
    const __half* x = g_bufH5;
    int b = blockIdx.x;
    int cbase = blockIdx.y * 128;
    __shared__ int s_lo, s_hi;
    if (threadIdx.x == 0) {
        s_lo = lower_bound_idx(batch, N, b);
        s_hi = lower_bound_idx(batch, N, b + 1);
    }
    __syncthreads();
    int lo = s_lo, hi = s_hi;
    float inv = 1.0f / fmaxf((float)(hi - lo), 1.0f);
    int c = cbase + threadIdx.x;
    float s0 = 0.f, s1 = 0.f, s2 = 0.f, s3 = 0.f;
    int n = lo;
    for (; n + 3 < hi; n += 4) {
        s0 += __half2float(x[(size_t)n * 512 + c]);
        s1 += __half2float(x[(size_t)(n + 1) * 512 + c]);
        s2 += __half2float(x[(size_t)(n + 2) * 512 + c]);
        s3 += __half2float(x[(size_t)(n + 3) * 512 + c]);
    }
    for (; n < hi; n++) s0 += __half2float(x[(size_t)n * 512 + c]);
    out[(size_t)b * 512 + c] = (s0 + s1 + s2 + s3) * inv;
}

// ---------------- launch ----------------
static inline unsigned gr(long long n, int b) { return (unsigned)((n + b - 1) / b); }

extern "C" void kernel_launch(void* const* d_in, const int* in_sizes, int n_in,
                              void* d_out, int out_size) {
    const float* x     = (const float*)d_in[0];
    const void*  ei    = d_in[1];
    const void*  batch = d_in[2];
    const float *W1 = (const float*)d_in[3],  *b1 = (const float*)d_in[4];
    const float *W2 = (const float*)d_in[5],  *b2 = (const float*)d_in[6];
    const float *W3 = (const float*)d_in[7],  *b3 = (const float*)d_in[8];
    const float *W4 = (const float*)d_in[9],  *b4 = (const float*)d_in[10];
    const float *W5 = (const float*)d_in[11], *b5 = (const float*)d_in[12];

    const int N = in_sizes[0] / 32;
    const int E = in_sizes[1] / 2;
    const int B = out_size / 512;

    const int TB = 256;
    const int A = 0, Bb = 1;
    const int nb = (N + 1023) / 1024;

    static int smem_set = 0;
    if (!smem_set) {
        cudaFuncSetAttribute(hgemm_kernel<1>, cudaFuncAttributeMaxDynamicSharedMemorySize, HGEMM_SMEM);
        cudaFuncSetAttribute(hgemm_kernel<2>, cudaFuncAttributeMaxDynamicSharedMemorySize, HGEMM_SMEM);
        smem_set = 1;
    }

    __half *h3;
    cudaGetSymbolAddress((void**)&h3, g_bufH3);
    __half *h2;
    cudaGetSymbolAddress((void**)&h2, g_bufH2);

    // CSR build + norms + weight transpose/convert
    zero_detect_kernel<<<gr(N, TB), TB>>>((const int*)ei, N);
    deg_accum_kernel<<<gr(E, TB), TB>>>(ei, E);
    scan_phase1<<<nb, 1024>>>(N);
    scan_phase3<<<nb, 1024>>>(N);
    fill_kernel<<<gr(E, TB), TB>>>(ei, E);
    trconv_both_kernel<<<dim3(16, 8, 2), dim3(32, 8)>>>(W4, W5);

    // Layer 1 (32 -> 8): mm1 -> bufA, gather -> bufB
    mm1_kernel<<<gr((long long)N * 8, TB), TB>>>(x, W1, N);
    gather_agg_kernel<2, 0><<<gr((long long)N * 2, TB), TB>>>(A, Bb, nullptr, N);

    // Layer 2 fused: gather relu(bufB+b1) (dim8) + mm 8->16 -> bufA (fp32)
    fused_gather_mm_kernel<8, 16, 128, 1, 0><<<gr(N, 128), 256>>>(Bb, A, b1, W2, b2, N);

    // Layer 3 fused: gather bufA (dim16) + mm 16->64 -> g_bufH3 (half)
    fused_gather_mm_kernel<16, 64, 64, 0, 1><<<gr(N, 64), 256>>>(A, Bb, nullptr, W3, b3, N);

    // Layer 4: gather x3 (half) -> half g_bufH; GEMM -> half x4.
    gather_agg_hh_kernel<16><<<gr((long long)N * 16, TB), TB>>>(h3, N);
    {
        dim3 grid(gr(N, 128), 256 / 128);
        hgemm_kernel<1><<<grid, 256, HGEMM_SMEM>>>(4, b4, N, 64, 256);
    }

    // Layer 5: gather x4 (half) -> half g_bufH; GEMM -> half x5.
    gather_agg_hh_kernel<64><<<gr((long long)N * 64, TB), TB>>>(h2, N);
    {
        dim3 grid(gr(N, 128), 512 / 128);
        hgemm_kernel<2><<<grid, 256, HGEMM_SMEM>>>(5, b5, N, 256, 512);
    }

    // Global mean pool from half x5
    dim3 pgrid(B, 4);
    pool_kernel<<<pgrid, 128>>>(batch, (float*)d_out, N, B);
}

// round 15
// speedup vs baseline: 1.0106x; 1.0106x over previous
#include <cuda_runtime.h>
#include <cuda_fp16.h>
#include <math.h>
#include <stdint.h>

// Problem constants (match reference_code)
#define NN 50000
#define EE 400000
#define BB 50

#define NB 296                      // mega-kernel grid (all-resident: 2/SM on 148 SMs)
#define NT (NB * 256)

// ---------------- scratch (static device allocations: allowed) ----------------
__device__ __align__(16) float  g_bufA[(size_t)NN * 8];    // mm1 out (h1)
__device__ __align__(16) float  g_bufB[(size_t)NN * 8];    // gather L1 out
__device__ __align__(16) float  g_bufC[(size_t)NN * 16];   // x2
__device__ __align__(16) __half g_bufH[(size_t)NN * 256];  // gather out (GEMM in)
__device__ __align__(16) __half g_bufH2[(size_t)NN * 256]; // x4
__device__ __align__(16) __half g_bufH3[(size_t)NN * 64];  // x3
__device__ __align__(16) __half g_bufH5[(size_t)NN * 512]; // x5
__device__ __align__(16) float  g_dinv[NN];
__device__ __align__(16) float  g_self[NN];
__device__ __align__(16) float  g_ew[EE];
__device__ __align__(16) __half g_w4h[256 * 64];
__device__ __align__(16) __half g_w5h[512 * 256];
__device__ int      g_degi[NN];
__device__ int      g_rowptr[NN + 1];
__device__ int      g_cursor[NN];
__device__ int      g_esrc[EE];
__device__ int      g_bsum[256];
__device__ int      g_is64;
__device__ unsigned g_bar_cnt;
__device__ unsigned g_bar_gen;

__device__ __forceinline__ int ld_idx(const void* p, long long i) {
    if (g_is64) return (int)((const long long*)p)[i];
    return ((const int*)p)[i];
}

__device__ __forceinline__ uint32_t smem_u32(const void* p) {
    uint32_t a;
    asm("{ .reg .u64 t; cvta.to.shared.u64 t, %1; cvt.u32.u64 %0, t; }" : "=r"(a) : "l"(p));
    return a;
}

// ---------------- software grid barrier (all NB blocks resident) -------------
__device__ __forceinline__ void grid_barrier() {
    __syncthreads();
    if (threadIdx.x == 0) {
        __threadfence();
        unsigned gen = atomicAdd(&g_bar_gen, 0u);
        unsigned arr = atomicAdd(&g_bar_cnt, 1u);
        if (arr == NB - 1) {
            atomicExch(&g_bar_cnt, 0u);
            __threadfence();
            atomicAdd(&g_bar_gen, 1u);
        } else {
            while (atomicAdd(&g_bar_gen, 0u) == gen) { __nanosleep(64); }
        }
    }
    __syncthreads();
}

// ============================================================================
// MEGA KERNEL: CSR build + norms + W transposes + mm1 + gather L1 + L2 + L3
// ============================================================================
__global__ __launch_bounds__(256, 2)
void mega_kernel(const float* __restrict__ x, const void* __restrict__ ei,
                 const float* __restrict__ W1, const float* __restrict__ b1,
                 const float* __restrict__ W2, const float* __restrict__ b2,
                 const float* __restrict__ W3, const float* __restrict__ b3,
                 const float* __restrict__ W4, const float* __restrict__ W5,
                 int N, int E) {
    __shared__ float s_ws[1024];
    __shared__ float s_agg[1024];
    __shared__ float s_bs[64];
    __shared__ int   s_redi[9];
    __shared__ int   s_offi;

    const int tid  = threadIdx.x;
    const int gtid = blockIdx.x * 256 + tid;
    const int lane = tid & 31, warp = tid >> 5;

    // ---- Phase A: zero degi, detect dtype, transpose W4/W5, mm1 ----
    for (int i = gtid; i < N; i += NT) g_degi[i] = 0;
    if (gtid == 0) {
        const int* e32 = (const int*)ei;
        int all0 = 1;
        for (int i = 1; i < 4096; i += 2)
            if (e32[i] != 0) { all0 = 0; break; }
        g_is64 = all0;
    }
    for (int o = gtid; o < 64 * 256; o += NT) {
        int r = o & 63, c = o >> 6;
        g_w4h[(size_t)c * 64 + r] = __float2half_rn(W4[(size_t)r * 256 + c]);
    }
    for (int o = gtid; o < 256 * 512; o += NT) {
        int r = o & 255, c = o >> 8;
        g_w5h[(size_t)c * 256 + r] = __float2half_rn(W5[(size_t)r * 512 + c]);
    }
    // mm1 (32 -> 8), W1 in smem
    for (int i = tid; i < 256; i += 256) s_ws[i] = W1[i];
    __syncthreads();
    for (long long it = gtid; it < (long long)N * 8; it += NT) {
        int n = (int)(it >> 3), c = (int)(it & 7);
        const float* xr = x + (size_t)n * 32;
        float acc = 0.0f;
#pragma unroll
        for (int k = 0; k < 32; k++) acc = fmaf(xr[k], s_ws[k * 8 + c], acc);
        g_bufA[(size_t)n * 8 + c] = acc;
    }
    grid_barrier();

    // ---- Phase B: degree accumulation ----
    for (int e = gtid; e < E; e += NT)
        atomicAdd(&g_degi[ld_idx(ei, (long long)E + e)], 1);
    grid_barrier();

    // ---- Phase C: per-chunk (256) inclusive scan ----
    {
        int nch = (N + 255) / 256;
        int b = blockIdx.x;
        if (b < nch) {
            int i = b * 256 + tid;
            int v = (i < N) ? __ldcg(&g_degi[i]) : 0;
            int incl = v;
#pragma unroll
            for (int off = 1; off < 32; off <<= 1) {
                int u = __shfl_up_sync(0xffffffffu, incl, off);
                if (lane >= off) incl += u;
            }
            if (lane == 31) s_redi[warp] = incl;
            __syncthreads();
            if (warp == 0 && lane < 8) {
                int w = s_redi[lane];
#pragma unroll
                for (int off = 1; off < 8; off <<= 1) {
                    int u = __shfl_up_sync(0x000000ffu, w, off);
                    if (lane >= off) w += u;
                }
                s_redi[lane] = w;
            }
            __syncthreads();
            if (warp > 0) incl += s_redi[warp - 1];
            if (i < N) g_rowptr[i] = incl;     // temp: chunk-local inclusive
            if (tid == 255) g_bsum[b] = incl;
        }
    }
    grid_barrier();

    // ---- Phase D: chunk offsets + finalize rowptr/cursor/dinv/self ----
    {
        int nch = (N + 255) / 256;
        int b = blockIdx.x;
        if (b < nch) {
            int v = (tid < b && tid < nch) ? g_bsum[tid] : 0;
            int s = v;
#pragma unroll
            for (int off = 16; off > 0; off >>= 1)
                s += __shfl_down_sync(0xffffffffu, s, off);
            if (lane == 0) s_redi[warp] = s;
            __syncthreads();
            if (tid == 0) {
                int t = 0;
#pragma unroll
                for (int j = 0; j < 8; j++) t += s_redi[j];
                s_offi = t;
            }
            __syncthreads();
            int offset = s_offi;
            int i = b * 256 + tid;
            if (i < N) {
                int dv   = __ldcg(&g_degi[i]);
                int incl = g_rowptr[i] + offset;
                int excl = incl - dv;
                g_rowptr[i] = excl;
                g_cursor[i] = excl;
                float d  = (float)dv + 1.0f;
                float di = rsqrtf(d);
                g_dinv[i] = di;
                g_self[i] = di * di;
                if (i == N - 1) g_rowptr[N] = incl;
            }
        }
    }
    grid_barrier();

    // ---- Phase E: CSR fill ----
    for (int e = gtid; e < E; e += NT) {
        int s = ld_idx(ei, e);
        int d = ld_idx(ei, (long long)E + e);
        int p = atomicAdd(&g_cursor[d], 1);
        g_esrc[p] = s;
        g_ew[p]   = g_dinv[s] * g_dinv[d];
    }
    grid_barrier();

    // ---- Phase F: gather L1 (dim 8): bufB = A_hat @ bufA ----
    for (long long it = gtid; it < (long long)N * 2; it += NT) {
        int n = (int)(it >> 1), c4 = (int)(it & 1);
        const float4* in4 = (const float4*)g_bufA;
        float4 acc = in4[(size_t)n * 2 + c4];
        float sn = g_self[n];
        acc.x *= sn; acc.y *= sn; acc.z *= sn; acc.w *= sn;
        int p0 = g_rowptr[n], p1 = g_rowptr[n + 1];
        for (int p = p0; p < p1; p++) {
            int   s = g_esrc[p];
            float w = g_ew[p];
            float4 v = in4[(size_t)s * 2 + c4];
            acc.x = fmaf(v.x, w, acc.x);
            acc.y = fmaf(v.y, w, acc.y);
            acc.z = fmaf(v.z, w, acc.z);
            acc.w = fmaf(v.w, w, acc.w);
        }
        ((float4*)g_bufB)[(size_t)n * 2 + c4] = acc;
    }
    grid_barrier();

    // ---- Phase G: fused L2: gather relu(bufB+b1) dim8 + mm 8->16 -> bufC ----
    for (int i = tid; i < 128; i += 256) s_ws[i] = W2[i];
    if (tid < 16) s_bs[tid] = b2[tid];
    {
        int ngroups = (N + 127) / 128;
        for (int g = blockIdx.x; g < ngroups; g += NB) {
            __syncthreads();
            // gather: nl = tid>>1, c4 = tid&1
            {
                int nl = tid >> 1, c4 = tid & 1;
                int n = g * 128 + nl;
                if (n < N) {
                    const float4* in4 = (const float4*)g_bufB;
                    float4 b = ((const float4*)b1)[c4];
                    float4 acc = in4[(size_t)n * 2 + c4];
                    acc.x = fmaxf(acc.x + b.x, 0.f);
                    acc.y = fmaxf(acc.y + b.y, 0.f);
                    acc.z = fmaxf(acc.z + b.z, 0.f);
                    acc.w = fmaxf(acc.w + b.w, 0.f);
                    float sn = g_self[n];
                    acc.x *= sn; acc.y *= sn; acc.z *= sn; acc.w *= sn;
                    int p0 = g_rowptr[n], p1 = g_rowptr[n + 1];
                    for (int p = p0; p < p1; p++) {
                        int   s = g_esrc[p];
                        float w = g_ew[p];
                        float4 v = in4[(size_t)s * 2 + c4];
                        v.x = fmaxf(v.x + b.x, 0.f);
                        v.y = fmaxf(v.y + b.y, 0.f);
                        v.z = fmaxf(v.z + b.z, 0.f);
                        v.w = fmaxf(v.w + b.w, 0.f);
                        acc.x = fmaf(v.x, w, acc.x);
                        acc.y = fmaf(v.y, w, acc.y);
                        acc.z = fmaf(v.z, w, acc.z);
                        acc.w = fmaf(v.w, w, acc.w);
                    }
                    *(float4*)&s_agg[nl * 8 + c4 * 4] = acc;
                }
            }
            __syncthreads();
            // matmul 8->16: 2 threads/node, 8 cols each
            {
                int nl = tid >> 1, cb = (tid & 1) * 8;
                int n = g * 128 + nl;
                if (n < N) {
                    float acc[8];
#pragma unroll
                    for (int j = 0; j < 8; j++) acc[j] = s_bs[cb + j];
#pragma unroll
                    for (int k = 0; k < 8; k++) {
                        float a = s_agg[nl * 8 + k];
#pragma unroll
                        for (int j = 0; j < 8; j++)
                            acc[j] = fmaf(a, s_ws[k * 16 + cb + j], acc[j]);
                    }
#pragma unroll
                    for (int j = 0; j < 8; j += 4) {
                        float4 o;
                        o.x = fmaxf(acc[j + 0], 0.f);
                        o.y = fmaxf(acc[j + 1], 0.f);
                        o.z = fmaxf(acc[j + 2], 0.f);
                        o.w = fmaxf(acc[j + 3], 0.f);
                        *(float4*)&g_bufC[(size_t)n * 16 + cb + j] = o;
                    }
                }
            }
        }
    }
    grid_barrier();

    // ---- Phase H: fused L3: gather bufC dim16 + mm 16->64 -> bufH3 (half) ----
    for (int i = tid; i < 1024; i += 256) s_ws[i] = W3[i];
    if (tid < 64) s_bs[tid] = b3[tid];
    {
        int ngroups = (N + 63) / 64;
        for (int g = blockIdx.x; g < ngroups; g += NB) {
            __syncthreads();
            {
                int nl = tid >> 2, c4 = tid & 3;
                int n = g * 64 + nl;
                if (n < N) {
                    const float4* in4 = (const float4*)g_bufC;
                    float4 acc = in4[(size_t)n * 4 + c4];
                    float sn = g_self[n];
                    acc.x *= sn; acc.y *= sn; acc.z *= sn; acc.w *= sn;
                    int p0 = g_rowptr[n], p1 = g_rowptr[n + 1];
                    for (int p = p0; p < p1; p++) {
                        int   s = g_esrc[p];
                        float w = g_ew[p];
                        float4 v = in4[(size_t)s * 4 + c4];
                        acc.x = fmaf(v.x, w, acc.x);
                        acc.y = fmaf(v.y, w, acc.y);
                        acc.z = fmaf(v.z, w, acc.z);
                        acc.w = fmaf(v.w, w, acc.w);
                    }
                    *(float4*)&s_agg[nl * 16 + c4 * 4] = acc;
                }
            }
            __syncthreads();
            {
                int nl = tid >> 2, cb = (tid & 3) * 16;
                int n = g * 64 + nl;
                if (n < N) {
                    float acc[16];
#pragma unroll
                    for (int j = 0; j < 16; j++) acc[j] = s_bs[cb + j];
#pragma unroll
                    for (int k = 0; k < 16; k++) {
                        float a = s_agg[nl * 16 + k];
#pragma unroll
                        for (int j = 0; j < 16; j++)
                            acc[j] = fmaf(a, s_ws[k * 64 + cb + j], acc[j]);
                    }
#pragma unroll
                    for (int j = 0; j < 16; j += 4) {
                        float v0 = fmaxf(acc[j + 0], 0.f);
                        float v1 = fmaxf(acc[j + 1], 0.f);
                        float v2 = fmaxf(acc[j + 2], 0.f);
                        float v3 = fmaxf(acc[j + 3], 0.f);
                        *(__half2*)&g_bufH3[(size_t)n * 64 + cb + j] =
                            __float22half2_rn(make_float2(v0, v1));
                        *(__half2*)&g_bufH3[(size_t)n * 64 + cb + j + 2] =
                            __float22half2_rn(make_float2(v2, v3));
                    }
                }
            }
        }
    }
}

// ---------------- CSR gather (half in, half out), unroll x2 ------------------
struct alignas(8) h4 { __half2 a, b; };
template <int D4>
__global__ void gather_agg_hh_kernel(const __half* __restrict__ in, int N) {
    int t = blockIdx.x * blockDim.x + threadIdx.x;
    int n = t / D4, c4 = t % D4;
    if (n >= N) return;
    const h4* in4 = (const h4*)in;

    h4 raw = in4[(size_t)n * D4 + c4];
    float2 l0 = __half22float2(raw.a), l1 = __half22float2(raw.b);
    float sn = g_self[n];
    float4 acc = make_float4(l0.x * sn, l0.y * sn, l1.x * sn, l1.y * sn);

    int p0 = g_rowptr[n], p1 = g_rowptr[n + 1];
    int p = p0;
    for (; p + 1 < p1; p += 2) {
        int   s0 = g_esrc[p],     s1 = g_esrc[p + 1];
        float w0 = g_ew[p];
        float w1 = g_ew[p + 1];
        h4 r0 = in4[(size_t)s0 * D4 + c4];
        h4 r1 = in4[(size_t)s1 * D4 + c4];
        float2 a0 = __half22float2(r0.a), a1 = __half22float2(r0.b);
        float2 b0 = __half22float2(r1.a), b1 = __half22float2(r1.b);
        acc.x = fmaf(a0.x, w0, acc.x); acc.y = fmaf(a0.y, w0, acc.y);
        acc.z = fmaf(a1.x, w0, acc.z); acc.w = fmaf(a1.y, w0, acc.w);
        acc.x = fmaf(b0.x, w1, acc.x); acc.y = fmaf(b0.y, w1, acc.y);
        acc.z = fmaf(b1.x, w1, acc.z); acc.w = fmaf(b1.y, w1, acc.w);
    }
    if (p < p1) {
        int   s = g_esrc[p];
        float w = g_ew[p];
        h4 rv = in4[(size_t)s * D4 + c4];
        float2 v0 = __half22float2(rv.a), v1 = __half22float2(rv.b);
        acc.x = fmaf(v0.x, w, acc.x); acc.y = fmaf(v0.y, w, acc.y);
        acc.z = fmaf(v1.x, w, acc.z); acc.w = fmaf(v1.y, w, acc.w);
    }
    h4 o;
    o.a = __float22half2_rn(make_float2(acc.x, acc.y));
    o.b = __float22half2_rn(make_float2(acc.z, acc.w));
    ((h4*)g_bufH)[(size_t)n * D4 + c4] = o;
}

// ---------------- fp16 m16n8k16 GEMM with cp.async 4-stage pipeline ----------
#define HSTAGES 4
#define H_PITCH 24
#define H_STG (128 * H_PITCH)
#define HGEMM_SMEM (HSTAGES * 2 * H_STG * 2)

template <int OUTSEL>
__global__ __launch_bounds__(256, 2)
void hgemm_kernel(int wsel, const float* __restrict__ bias,
                  int N, int K, int OUT) {
    extern __shared__ __half smh[];
    const uint32_t sbase = smem_u32(smh);

    const __half* Ah = g_bufH;
    const __half* Wt = (wsel == 4) ? g_w4h : g_w5h;
    __half*       Ch = (OUTSEL == 1) ? g_bufH2 : g_bufH5;

    const int tid    = threadIdx.x;
    const int lane   = tid & 31;
    const int warpId = tid >> 5;
    const int warpM  = warpId & 1;
    const int warpN  = warpId >> 1;
    const int gid    = lane >> 2;
    const int tig    = lane & 3;
    const int block_row = blockIdx.x * 128;
    const int block_col = blockIdx.y * 128;

    float c[4][4][4];
#pragma unroll
    for (int i = 0; i < 4; i++)
#pragma unroll
        for (int j = 0; j < 4; j++)
#pragma unroll
            for (int r = 0; r < 4; r++) c[i][j][r] = 0.0f;

    auto load_stage = [&](int st, int k0) {
#pragma unroll
        for (int it = 0; it < 2; it++) {
            int chunk = tid + it * 256;
            if (chunk < 256) {
                int r = chunk >> 1, c8 = (chunk & 1) * 8;
                int grow = block_row + r;
                const __half* src = &Ah[(size_t)grow * K + k0 + c8];
                uint32_t dst = sbase + (st * H_STG + r * H_PITCH + c8) * 2;
                uint32_t pred = (grow < N) ? 1u : 0u;
                asm volatile(
                    "{ .reg .pred p; setp.ne.u32 p, %2, 0;\n\t"
                    "@p cp.async.cg.shared.global [%0], [%1], 16; }"
                    :: "r"(dst), "l"(src), "r"(pred) : "memory");
            } else {
                int c2 = chunk - 256;
                int r = c2 >> 1, c8 = (c2 & 1) * 8;
                const __half* src = &Wt[(size_t)(block_col + r) * K + k0 + c8];
                uint32_t dst = sbase + (HSTAGES * H_STG + st * H_STG + r * H_PITCH + c8) * 2;
                asm volatile("cp.async.cg.shared.global [%0], [%1], 16;"
                             :: "r"(dst), "l"(src) : "memory");
            }
        }
    };

    const int ntiles = K >> 4;
    const int pre = (ntiles < 3) ? ntiles : 3;
    for (int st = 0; st < pre; st++) {
        load_stage(st, st * 16);
        asm volatile("cp.async.commit_group;" ::: "memory");
    }

    for (int ti = 0; ti < ntiles; ti++) {
        asm volatile("cp.async.wait_group 2;" ::: "memory");
        __syncthreads();
        int nxt = ti + 3;
        if (nxt < ntiles) load_stage(nxt & 3, nxt * 16);
        asm volatile("cp.async.commit_group;" ::: "memory");

        const int st = ti & 3;
        const __half* As = &smh[st * H_STG];
        const __half* Bs = &smh[HSTAGES * H_STG + st * H_STG];

        unsigned a[4][4], b[4][2];
#pragma unroll
        for (int mt = 0; mt < 4; mt++) {
            int mb = warpM * 64 + mt * 16;
            a[mt][0] = *(const unsigned*)&As[(mb + gid) * H_PITCH + 2 * tig];
            a[mt][1] = *(const unsigned*)&As[(mb + gid + 8) * H_PITCH + 2 * tig];
            a[mt][2] = *(const unsigned*)&As[(mb + gid) * H_PITCH + 2 * tig + 8];
            a[mt][3] = *(const unsigned*)&As[(mb + gid + 8) * H_PITCH + 2 * tig + 8];
        }
#pragma unroll
        for (int nt = 0; nt < 4; nt++) {
            int nb = warpN * 32 + nt * 8;
            b[nt][0] = *(const unsigned*)&Bs[(nb + gid) * H_PITCH + 2 * tig];
            b[nt][1] = *(const unsigned*)&Bs[(nb + gid) * H_PITCH + 2 * tig + 8];
        }
#pragma unroll
        for (int mt = 0; mt < 4; mt++)
#pragma unroll
            for (int nt = 0; nt < 4; nt++) {
                asm volatile(
                    "mma.sync.aligned.m16n8k16.row.col.f32.f16.f16.f32 "
                    "{%0,%1,%2,%3}, {%4,%5,%6,%7}, {%8,%9}, {%0,%1,%2,%3};"
                    : "+f"(c[mt][nt][0]), "+f"(c[mt][nt][1]),
                      "+f"(c[mt][nt][2]), "+f"(c[mt][nt][3])
                    : "r"(a[mt][0]), "r"(a[mt][1]), "r"(a[mt][2]), "r"(a[mt][3]),
                      "r"(b[nt][0]), "r"(b[nt][1]));
            }
    }

    // Epilogue: bias + relu -> half
#pragma unroll
    for (int mt = 0; mt < 4; mt++) {
        int row0 = block_row + warpM * 64 + mt * 16 + gid;
#pragma unroll
        for (int nt = 0; nt < 4; nt++) {
            int col = block_col + warpN * 32 + nt * 8 + tig * 2;
            float bx = bias[col], by = bias[col + 1];
            float v0x = fmaxf(c[mt][nt][0] + bx, 0.f);
            float v0y = fmaxf(c[mt][nt][1] + by, 0.f);
            float v1x = fmaxf(c[mt][nt][2] + bx, 0.f);
            float v1y = fmaxf(c[mt][nt][3] + by, 0.f);
            if (row0 < N)
                *(__half2*)&Ch[(size_t)row0 * OUT + col] =
                    __float22half2_rn(make_float2(v0x, v0y));
            if (row0 + 8 < N)
                *(__half2*)&Ch[(size_t)(row0 + 8) * OUT + col] =
                    __float22half2_rn(make_float2(v1x, v1y));
        }
    }
}

// ---------------- mean pool over sorted batch ids (half x5 input) -----------
__device__ __forceinline__ int lower_bound_idx(const void* a, int n, int v) {
    int lo = 0, hi = n;
    while (lo < hi) {
        int m = (lo + hi) >> 1;
        if (ld_idx(a, m) < v) lo = m + 1; else hi = m;
    }
    return lo;
}

__global__ void pool_kernel(const void* __restrict__ batch,
                            float* __restrict__ out, int N, int B) {
    const __half* x = g_bufH5;
    int b = blockIdx.x;
    int cbase = blockIdx.y * 128;
    __shared__ int s_lo, s_hi;
    if (threadIdx.x == 0) {
        s_lo = lower_bound_idx(batch, N, b);
        s_hi = lower_bound_idx(batch, N, b + 1);
    }
    __syncthreads();
    int lo = s_lo, hi = s_hi;
    float inv = 1.0f / fmaxf((float)(hi - lo), 1.0f);
    int c = cbase + threadIdx.x;
    float s0 = 0.f, s1 = 0.f, s2 = 0.f, s3 = 0.f;
    int n = lo;
    for (; n + 3 < hi; n += 4) {
        s0 += __half2float(x[(size_t)n * 512 + c]);
        s1 += __half2float(x[(size_t)(n + 1) * 512 + c]);
        s2 += __half2float(x[(size_t)(n + 2) * 512 + c]);
        s3 += __half2float(x[(size_t)(n + 3) * 512 + c]);
    }
    for (; n < hi; n++) s0 += __half2float(x[(size_t)n * 512 + c]);
    out[(size_t)b * 512 + c] = (s0 + s1 + s2 + s3) * inv;
}

// ---------------- launch ----------------
static inline unsigned gr(long long n, int b) { return (unsigned)((n + b - 1) / b); }

extern "C" void kernel_launch(void* const* d_in, const int* in_sizes, int n_in,
                              void* d_out, int out_size) {
    const float* x     = (const float*)d_in[0];
    const void*  ei    = d_in[1];
    const void*  batch = d_in[2];
    const float *W1 = (const float*)d_in[3],  *b1 = (const float*)d_in[4];
    const float *W2 = (const float*)d_in[5],  *b2 = (const float*)d_in[6];
    const float *W3 = (const float*)d_in[7],  *b3 = (const float*)d_in[8];
    const float *W4 = (const float*)d_in[9],  *b4 = (const float*)d_in[10];
    const float *W5 = (const float*)d_in[11], *b5 = (const float*)d_in[12];

    const int N = in_sizes[0] / 32;
    const int E = in_sizes[1] / 2;
    const int B = out_size / 512;

    static int smem_set = 0;
    if (!smem_set) {
        cudaFuncSetAttribute(hgemm_kernel<1>, cudaFuncAttributeMaxDynamicSharedMemorySize, HGEMM_SMEM);
        cudaFuncSetAttribute(hgemm_kernel<2>, cudaFuncAttributeMaxDynamicSharedMemorySize, HGEMM_SMEM);
        smem_set = 1;
    }

    __half *h3, *h2;
    cudaGetSymbolAddress((void**)&h3, g_bufH3);
    cudaGetSymbolAddress((void**)&h2, g_bufH2);

    // 1) mega kernel: CSR + norms + transposes + mm1 + L1 gather + L2 + L3
    mega_kernel<<<NB, 256>>>(x, ei, W1, b1, W2, b2, W3, b3, W4, W5, N, E);

    // 2) Layer 4 gather: x3 (half) -> g_bufH
    gather_agg_hh_kernel<16><<<gr((long long)N * 16, 256), 256>>>(h3, N);

    // 3) Layer 4 GEMM (64 -> 256) -> half x4
    {
        dim3 grid(gr(N, 128), 256 / 128);
        hgemm_kernel<1><<<grid, 256, HGEMM_SMEM>>>(4, b4, N, 64, 256);
    }

    // 4) Layer 5 gather: x4 (half) -> g_bufH
    gather_agg_hh_kernel<64><<<gr((long long)N * 64, 256), 256>>>(h2, N);

    // 5) Layer 5 GEMM (256 -> 512) -> half x5
    {
        dim3 grid(gr(N, 128), 512 / 128);
        hgemm_kernel<2><<<grid, 256, HGEMM_SMEM>>>(5, b5, N, 256, 512);
    }

    // 6) Global mean pool
    dim3 pgrid(B, 4);
    pool_kernel<<<pgrid, 128>>>(batch, (float*)d_out, N, B);
}